// round 11
// baseline (speedup 1.0000x reference)
#include <cuda_runtime.h>
#include <cuda_fp16.h>
#include <cstdint>

// B=1, H=128, S=256, D=2048, fp32 in/out.
#define HH 128
#define SS 256
#define DD 2048

// ---------------------------------------------------------------------------
// Helpers
// ---------------------------------------------------------------------------
__device__ __forceinline__ uint32_t smem_to_u32(const void* p) {
  uint32_t a;
  asm("{ .reg .u64 t; cvta.to.shared.u64 t, %1; cvt.u32.u64 %0, t; }" : "=r"(a) : "l"(p));
  return a;
}
#define SWZ(o) ((o) ^ (((o) >> 3) & 0x70))

__device__ __forceinline__ void cp_async16(uint32_t dst, const void* src) {
  asm volatile("cp.async.cg.shared.global [%0], [%1], 16;" :: "r"(dst), "l"(src) : "memory");
}
__device__ __forceinline__ void cp_commit() {
  asm volatile("cp.async.commit_group;" ::: "memory");
}
__device__ __forceinline__ void cp_wait0() {
  asm volatile("cp.async.wait_group 0;" ::: "memory");
}
__device__ __forceinline__ void cp_wait1() {
  asm volatile("cp.async.wait_group 1;" ::: "memory");
}

__device__ __forceinline__ void ldsm_x4(uint32_t addr, uint32_t* r) {
  asm volatile("ldmatrix.sync.aligned.m8n8.x4.shared.b16 {%0,%1,%2,%3}, [%4];"
               : "=r"(r[0]), "=r"(r[1]), "=r"(r[2]), "=r"(r[3]) : "r"(addr));
}
__device__ __forceinline__ void ldsm_x4_t(uint32_t addr, uint32_t* r) {
  asm volatile("ldmatrix.sync.aligned.m8n8.x4.trans.shared.b16 {%0,%1,%2,%3}, [%4];"
               : "=r"(r[0]), "=r"(r[1]), "=r"(r[2]), "=r"(r[3]) : "r"(addr));
}

__device__ __forceinline__ void mma16816(float* c, const uint32_t* a, const uint32_t* b) {
  asm volatile(
      "mma.sync.aligned.m16n8k16.row.col.f32.f16.f16.f32 "
      "{%0,%1,%2,%3}, {%4,%5,%6,%7}, {%8,%9}, {%0,%1,%2,%3};"
      : "+f"(c[0]), "+f"(c[1]), "+f"(c[2]), "+f"(c[3])
      : "r"(a[0]), "r"(a[1]), "r"(a[2]), "r"(a[3]), "r"(b[0]), "r"(b[1]));
}

__device__ __forceinline__ void sts8h(uint32_t addr, __half a, __half b,
                                      __half c, __half d) {
  __half2 p0(a, b), p1(c, d);
  asm volatile("st.shared.v2.b32 [%0], {%1, %2};" ::
               "r"(addr), "r"(*(uint32_t*)&p0), "r"(*(uint32_t*)&p1) : "memory");
}
__device__ __forceinline__ void sts4h2(uint32_t addr, __half2 p) {
  asm volatile("st.shared.b32 [%0], %1;" :: "r"(addr), "r"(*(uint32_t*)&p) : "memory");
}

// Window tile rows: 128B hold 64 k fp16 = two 32-k chunks; p = chunk parity
// selects the 64B half; ks = 16-k step within chunk. SW128 swizzled.
__device__ __forceinline__ uint32_t a_frag_addr(uint32_t tb, int mt, int ks, int p, int lid) {
  uint32_t off = (uint32_t)(mt + (lid & 15)) * 128 + p * 64 + ks * 32 + ((lid >> 4) * 16);
  return tb + SWZ(off);
}
__device__ __forceinline__ uint32_t b_frag_addr(uint32_t tb, int nt, int ks, int p, int lid) {
  uint32_t off = (uint32_t)(nt + ((lid >> 4) & 1) * 8 + (lid & 7)) * 128
               + p * 64 + ks * 32 + (((lid >> 3) & 1) * 16);
  return tb + SWZ(off);
}
// V trans tile (64-d slice): rows = s (256 x 128B), cols = 64 d fp16.
__device__ __forceinline__ uint32_t v_frag_addr(uint32_t vbase, int krow, int nt, int lid) {
  uint32_t row = (uint32_t)(krow + ((lid >> 3) & 1) * 8 + (lid & 7));
  uint32_t col = (uint32_t)(nt + ((lid >> 4) & 1) * 8) * 2;
  return vbase + SWZ(row * 128 + col);
}

// ---------------------------------------------------------------------------
// JAX threefry2x32 (20 rounds) — exact; partitionable counter layout.
// ---------------------------------------------------------------------------
__device__ __forceinline__ uint32_t rotl32(uint32_t x, int r) {
  return (x << r) | (x >> (32 - r));
}
__device__ __forceinline__ void threefry2x32(uint32_t k0, uint32_t k1,
                                             uint32_t& x0, uint32_t& x1) {
  const uint32_t ks0 = k0, ks1 = k1, ks2 = k0 ^ k1 ^ 0x1BD11BDAu;
  x0 += ks0; x1 += ks1;
#define TF_R(r) { x0 += x1; x1 = rotl32(x1, r); x1 ^= x0; }
  TF_R(13) TF_R(15) TF_R(26) TF_R(6)
  x0 += ks1; x1 += ks2 + 1u;
  TF_R(17) TF_R(29) TF_R(16) TF_R(24)
  x0 += ks2; x1 += ks0 + 2u;
  TF_R(13) TF_R(15) TF_R(26) TF_R(6)
  x0 += ks0; x1 += ks1 + 3u;
  TF_R(17) TF_R(29) TF_R(16) TF_R(24)
  x0 += ks1; x1 += ks2 + 4u;
  TF_R(13) TF_R(15) TF_R(26) TF_R(6)
  x0 += ks2; x1 += ks0 + 5u;
#undef TF_R
}
__device__ __forceinline__ bool keep_draw(uint32_t i) {
  uint32_t x0 = 0u, x1 = i;
  threefry2x32(0u, 42u, x0, x1);
  const uint32_t bits = x0 ^ x1;
  const float u = __uint_as_float((bits >> 9) | 0x3F800000u) - 1.0f;
  return u < 0.1f;
}

// ===========================================================================
// FUSED kernel: QK^T + scale + mask + softmax + dropout (P in smem) + PV.
// Grid (2, HH), 512 threads, 1 CTA/SM.
// Phase A smem: QF(0..1) 2x48KB @0 ; QA(0..1) 2x16KB @98304 ; QB(0..1)
//   2x32KB @131072.  (ends 196608)
// Phase B smem (overlays dead phase-A regions):
//   P windows PW(0..3) 4x16KB @4096 ; V fp32 stage VSB 64KB @69632 ;
//   V fp16 tiles VT(0..1) 2x32KB @135168.  (ends 200704)
// ===========================================================================
#define QF(s) (sbase + (uint32_t)(s) * 49152u)
#define QA(w) (sbase + 98304u + (uint32_t)(w) * 16384u)
#define QB(w) (sbase + 131072u + (uint32_t)(w) * 32768u)
#define PW(w) (sbase + 4096u + (uint32_t)(w) * 16384u)
#define VSB   (sbase + 69632u)
#define VT(i) (sbase + 135168u + (uint32_t)(i) * 32768u)
#define FUSED_SMEM 200704

__device__ __forceinline__ void qks_cp(
    uint32_t fbase, const float* __restrict__ Qf, const float* __restrict__ Kf,
    size_t qrow0, size_t krow0, int kb, int tid) {
#pragma unroll
  for (int i = 0; i < 6; i++) {
    int seg = tid + i * 512;            // 0..3071 : 1024 A + 2048 B
    int tile = (seg >= 1024);
    int w = tile ? seg - 1024 : seg;
    int r = w >> 3, c4 = w & 7;
    const float* g = tile ? (Kf + (krow0 + r) * DD) : (Qf + (qrow0 + r) * DD);
    cp_async16(fbase + (tile ? 16384u : 0u) + (uint32_t)w * 16u, g + kb + c4 * 4);
  }
  cp_commit();
}

__device__ __forceinline__ void qks_convert(uint32_t fbase, uint32_t taw,
                                            uint32_t tbw, int p, int tid) {
#pragma unroll
  for (int i = 0; i < 6; i++) {
    int seg = tid + i * 512;
    int tile = (seg >= 1024);
    int w = tile ? seg - 1024 : seg;
    uint32_t faddr = fbase + (tile ? 16384u : 0u) + (uint32_t)w * 16u;
    float4 v;
    asm volatile("ld.shared.v4.b32 {%0,%1,%2,%3}, [%4];"
                 : "=f"(v.x), "=f"(v.y), "=f"(v.z), "=f"(v.w) : "r"(faddr));
    __half h0 = __float2half(v.x), h1 = __float2half(v.y);
    __half h2 = __float2half(v.z), h3 = __float2half(v.w);
    int r = w >> 3, c4 = w & 7;
    uint32_t base = tile ? tbw : taw;
    uint32_t o = (uint32_t)r * 128u + (uint32_t)p * 64u + (uint32_t)c4 * 8u;
    sts8h(base + SWZ(o), h0, h1, h2, h3);
  }
}

__device__ __forceinline__ void v_cp_chunk(
    uint32_t vsb, const float* __restrict__ Vf, size_t vrow0, int dc, int tid) {
#pragma unroll
  for (int i = 0; i < 8; i++) {
    int w = tid + i * 512;              // 0..4095 : 256 s x 16 float4
    int sl = w >> 4, f4 = w & 15;
    cp_async16(vsb + (uint32_t)w * 16u, Vf + (vrow0 + sl) * DD + dc * 64 + f4 * 4);
  }
  cp_commit();
}

__device__ __forceinline__ void v_convert(uint32_t vsb, uint32_t vt, int tid) {
#pragma unroll
  for (int i = 0; i < 8; i++) {
    int w = tid + i * 512;
    int sl = w >> 4, f4 = w & 15;
    float4 v;
    asm volatile("ld.shared.v4.b32 {%0,%1,%2,%3}, [%4];"
                 : "=f"(v.x), "=f"(v.y), "=f"(v.z), "=f"(v.w)
                 : "r"(vsb + (uint32_t)w * 16u));
    sts8h(vt + SWZ((uint32_t)sl * 128u + (uint32_t)f4 * 8u),
          __float2half(v.x), __float2half(v.y),
          __float2half(v.z), __float2half(v.w));
  }
}

__global__ __launch_bounds__(512, 1) void attn_kernel(
    const float* __restrict__ Qf, const float* __restrict__ Kf,
    const float* __restrict__ Vf, const float* __restrict__ mask,
    float* __restrict__ out) {
  extern __shared__ char smem[];
  const uint32_t sbase = smem_to_u32(smem);
  const int tid = threadIdx.x, wid = tid >> 5, lid = tid & 31;
  const int warp_m = wid >> 2, warp_n = wid & 3;
  const int m0 = warp_m * 32, n0 = warp_n * 64;
  const int q0 = blockIdx.x * 128;
  const int h = blockIdx.y;

  const size_t qrow0 = (size_t)h * SS + q0;
  const size_t krow0 = (size_t)h * SS;
  const size_t vrow0 = (size_t)h * SS;

  // =========================== Phase A: QK scores =========================
  float acc[2][8][4];
#pragma unroll
  for (int mi = 0; mi < 2; mi++)
#pragma unroll
    for (int ni = 0; ni < 8; ni++)
#pragma unroll
      for (int j = 0; j < 4; j++) acc[mi][ni][j] = 0.0f;

  const int NC = DD / 32;  // 64
  qks_cp(QF(0), Qf, Kf, qrow0, krow0, 0, tid);
  qks_cp(QF(1), Qf, Kf, qrow0, krow0, 32, tid);
  cp_wait1();
  qks_convert(QF(0), QA(0), QB(0), 0, tid);
  __syncthreads();

  for (int ck = 0; ck < NC; ck++) {
    const bool have2 = (ck + 2 < NC);
    if (have2) qks_cp(QF(ck & 1), Qf, Kf, qrow0, krow0, (ck + 2) * 32, tid);
    // 1-term MMA on window halves
    {
      const uint32_t taw = QA((ck >> 1) & 1), tbw = QB((ck >> 1) & 1);
      const int p = ck & 1;
#pragma unroll
      for (int ks = 0; ks < 2; ks++) {
        uint32_t a[2][4], b[4][4];
#pragma unroll
        for (int mi = 0; mi < 2; mi++)
          ldsm_x4(a_frag_addr(taw, m0 + mi * 16, ks, p, lid), a[mi]);
#pragma unroll
        for (int nj = 0; nj < 4; nj++)
          ldsm_x4(b_frag_addr(tbw, n0 + nj * 16, ks, p, lid), b[nj]);
#pragma unroll
        for (int mi = 0; mi < 2; mi++)
#pragma unroll
          for (int ni = 0; ni < 8; ni++) {
            uint32_t bb[2] = { b[ni >> 1][(ni & 1) * 2], b[ni >> 1][(ni & 1) * 2 + 1] };
            mma16816(acc[mi][ni], a[mi], bb);
          }
      }
    }
    if (ck + 1 < NC) {
      if (have2) cp_wait1(); else cp_wait0();
      qks_convert(QF((ck + 1) & 1), QA(((ck + 1) >> 1) & 1), QB(((ck + 1) >> 1) & 1),
                  (ck + 1) & 1, tid);
    }
    __syncthreads();
  }

  // ---- scale + mask ----
  const float scale = 0.022097086912079608f;  // 1/sqrt(2048)
  const int rr = lid >> 2, cc = lid & 3;
#pragma unroll
  for (int mi = 0; mi < 2; mi++)
#pragma unroll
    for (int ni = 0; ni < 8; ni++)
#pragma unroll
      for (int j = 0; j < 4; j++) {
        const int r = q0 + m0 + mi * 16 + (j >> 1) * 8 + rr;
        const int c = n0 + ni * 8 + cc * 2 + (j & 1);
        acc[mi][ni][j] = acc[mi][ni][j] * scale + mask[(size_t)r * SS + c];
      }

  // ---- row softmax across 4 n-warps ----
  float* sred = (float*)smem;  // [128 rows][4]  (@0..2048, below PW)
  float rmax[2][2], rsum[2][2];
#pragma unroll
  for (int mi = 0; mi < 2; mi++)
#pragma unroll
    for (int hf = 0; hf < 2; hf++) {
      float m = -3.4e38f;
#pragma unroll
      for (int ni = 0; ni < 8; ni++) {
        m = fmaxf(m, acc[mi][ni][hf * 2 + 0]);
        m = fmaxf(m, acc[mi][ni][hf * 2 + 1]);
      }
      m = fmaxf(m, __shfl_xor_sync(0xffffffffu, m, 1));
      m = fmaxf(m, __shfl_xor_sync(0xffffffffu, m, 2));
      if (cc == 0) sred[(m0 + mi * 16 + hf * 8 + rr) * 4 + warp_n] = m;
    }
  __syncthreads();
#pragma unroll
  for (int mi = 0; mi < 2; mi++)
#pragma unroll
    for (int hf = 0; hf < 2; hf++) {
      const int row = m0 + mi * 16 + hf * 8 + rr;
      rmax[mi][hf] = fmaxf(fmaxf(sred[row * 4 + 0], sred[row * 4 + 1]),
                           fmaxf(sred[row * 4 + 2], sred[row * 4 + 3]));
    }
  __syncthreads();
#pragma unroll
  for (int mi = 0; mi < 2; mi++)
#pragma unroll
    for (int hf = 0; hf < 2; hf++) {
      float s = 0.0f;
#pragma unroll
      for (int ni = 0; ni < 8; ni++) {
        float e0 = expf(acc[mi][ni][hf * 2 + 0] - rmax[mi][hf]);
        float e1 = expf(acc[mi][ni][hf * 2 + 1] - rmax[mi][hf]);
        acc[mi][ni][hf * 2 + 0] = e0;
        acc[mi][ni][hf * 2 + 1] = e1;
        s += e0 + e1;
      }
      s += __shfl_xor_sync(0xffffffffu, s, 1);
      s += __shfl_xor_sync(0xffffffffu, s, 2);
      if (cc == 0) sred[(m0 + mi * 16 + hf * 8 + rr) * 4 + warp_n] = s;
    }
  __syncthreads();
#pragma unroll
  for (int mi = 0; mi < 2; mi++)
#pragma unroll
    for (int hf = 0; hf < 2; hf++) {
      const int row = m0 + mi * 16 + hf * 8 + rr;
      rsum[mi][hf] = sred[row * 4 + 0] + sred[row * 4 + 1] +
                     sred[row * 4 + 2] + sred[row * 4 + 3];
    }
  __syncthreads();  // sred reads done; PW stores may begin

  // ---- dropout + store P into smem windows (ldsm A-tile format) ----
#pragma unroll
  for (int mi = 0; mi < 2; mi++)
#pragma unroll
    for (int hf = 0; hf < 2; hf++) {
      const int rl = m0 + mi * 16 + hf * 8 + rr;       // local q row
      const float inv = 1.0f / rsum[mi][hf];
      const uint32_t ibase = ((uint32_t)h * SS + (uint32_t)(q0 + rl)) * SS;
#pragma unroll
      for (int ni = 0; ni < 8; ni++) {
        const int c = n0 + ni * 8 + cc * 2;
        float p0 = acc[mi][ni][hf * 2 + 0] * inv;
        float p1 = acc[mi][ni][hf * 2 + 1] * inv;
        p0 = keep_draw(ibase + c)     ? (p0 / 0.1f) : 0.0f;
        p1 = keep_draw(ibase + c + 1) ? (p1 / 0.1f) : 0.0f;
        sts4h2(PW(c >> 6) + SWZ((uint32_t)rl * 128u + (uint32_t)(c & 63) * 2u),
               __half2(__float2half(p0), __float2half(p1)));
      }
    }
  __syncthreads();  // P visible to all warps

  // =========================== Phase B: PV ================================
  const int NDC = DD / 64;  // 32
  v_cp_chunk(VSB, Vf, vrow0, 0, tid);
  cp_wait0();
  __syncthreads();
  v_convert(VSB, VT(0), tid);
  __syncthreads();
  v_cp_chunk(VSB, Vf, vrow0, 1, tid);

  const int nt = warp_n * 16;
  for (int dc = 0; dc < NDC; dc++) {
    float acc2[2][2][4];
#pragma unroll
    for (int mi = 0; mi < 2; mi++)
#pragma unroll
      for (int n = 0; n < 2; n++)
#pragma unroll
        for (int j = 0; j < 4; j++) acc2[mi][n][j] = 0.0f;

    const uint32_t vt = VT(dc & 1);
#pragma unroll
    for (int kb = 0; kb < 4; kb++)
#pragma unroll
      for (int p = 0; p < 2; p++)
#pragma unroll
        for (int ks = 0; ks < 2; ks++) {
          uint32_t a[2][4], b[4];
#pragma unroll
          for (int mi = 0; mi < 2; mi++)
            ldsm_x4(a_frag_addr(PW(kb), m0 + mi * 16, ks, p, lid), a[mi]);
          ldsm_x4_t(v_frag_addr(vt, kb * 64 + p * 32 + ks * 16, nt, lid), b);
#pragma unroll
          for (int mi = 0; mi < 2; mi++)
#pragma unroll
            for (int n = 0; n < 2; n++) {
              uint32_t bb[2] = { b[n * 2], b[n * 2 + 1] };
              mma16816(acc2[mi][n], a[mi], bb);
            }
        }

    // write out tile 128q x 64d
#pragma unroll
    for (int mi = 0; mi < 2; mi++) {
      const int r0 = q0 + m0 + mi * 16 + (lid >> 2);
#pragma unroll
      for (int n = 0; n < 2; n++) {
        const int c = dc * 64 + nt + n * 8 + (lid & 3) * 2;
#pragma unroll
        for (int half = 0; half < 2; half++) {
          const int r = r0 + half * 8;
          *(float2*)(out + ((size_t)h * SS + r) * DD + c) =
              make_float2(acc2[mi][n][half * 2 + 0], acc2[mi][n][half * 2 + 1]);
        }
      }
    }

    if (dc + 1 < NDC) {
      cp_wait0();
      __syncthreads();
      v_convert(VSB, VT((dc + 1) & 1), tid);
      __syncthreads();
      if (dc + 2 < NDC) v_cp_chunk(VSB, Vf, vrow0, dc + 2, tid);
    }
  }
}

// ---------------------------------------------------------------------------
// Launch
// ---------------------------------------------------------------------------
extern "C" void kernel_launch(void* const* d_in, const int* in_sizes, int n_in,
                              void* d_out, int out_size) {
  const float* Q = (const float*)d_in[0];
  const float* K = (const float*)d_in[1];
  const float* V = (const float*)d_in[2];
  const float* mask = (const float*)d_in[3];
  float* out = (float*)d_out;

  cudaFuncSetAttribute(attn_kernel, cudaFuncAttributeMaxDynamicSharedMemorySize,
                       FUSED_SMEM);
  attn_kernel<<<dim3(2, HH), 512, FUSED_SMEM>>>(Q, K, V, mask, out);
}

// round 12
// speedup vs baseline: 1.1039x; 1.1039x over previous
#include <cuda_runtime.h>
#include <cuda_fp16.h>
#include <cstdint>

// B=1, H=128, S=256, D=2048, fp32 in/out.
#define HH 128
#define SS 256
#define DD 2048

// ---------------------------------------------------------------------------
// Device scratch (no allocs allowed anywhere).
// ---------------------------------------------------------------------------
__device__ __half g_phi[(size_t)HH * SS * SS];    // P fp16 [h,q,s]

// ---------------------------------------------------------------------------
// Helpers
// ---------------------------------------------------------------------------
__device__ __forceinline__ uint32_t smem_to_u32(const void* p) {
  uint32_t a;
  asm("{ .reg .u64 t; cvta.to.shared.u64 t, %1; cvt.u32.u64 %0, t; }" : "=r"(a) : "l"(p));
  return a;
}
#define SWZ(o) ((o) ^ (((o) >> 3) & 0x70))

__device__ __forceinline__ void cp_async16(uint32_t dst, const void* src) {
  asm volatile("cp.async.cg.shared.global [%0], [%1], 16;" :: "r"(dst), "l"(src) : "memory");
}
__device__ __forceinline__ void cp_commit() {
  asm volatile("cp.async.commit_group;" ::: "memory");
}
__device__ __forceinline__ void cp_wait0() {
  asm volatile("cp.async.wait_group 0;" ::: "memory");
}
__device__ __forceinline__ void cp_wait1() {
  asm volatile("cp.async.wait_group 1;" ::: "memory");
}
__device__ __forceinline__ void cp_wait2() {
  asm volatile("cp.async.wait_group 2;" ::: "memory");
}

__device__ __forceinline__ void ldsm_x4(uint32_t addr, uint32_t* r) {
  asm volatile("ldmatrix.sync.aligned.m8n8.x4.shared.b16 {%0,%1,%2,%3}, [%4];"
               : "=r"(r[0]), "=r"(r[1]), "=r"(r[2]), "=r"(r[3]) : "r"(addr));
}
__device__ __forceinline__ void ldsm_x4_t(uint32_t addr, uint32_t* r) {
  asm volatile("ldmatrix.sync.aligned.m8n8.x4.trans.shared.b16 {%0,%1,%2,%3}, [%4];"
               : "=r"(r[0]), "=r"(r[1]), "=r"(r[2]), "=r"(r[3]) : "r"(addr));
}

__device__ __forceinline__ void mma16816(float* c, const uint32_t* a, const uint32_t* b) {
  asm volatile(
      "mma.sync.aligned.m16n8k16.row.col.f32.f16.f16.f32 "
      "{%0,%1,%2,%3}, {%4,%5,%6,%7}, {%8,%9}, {%0,%1,%2,%3};"
      : "+f"(c[0]), "+f"(c[1]), "+f"(c[2]), "+f"(c[3])
      : "r"(a[0]), "r"(a[1]), "r"(a[2]), "r"(a[3]), "r"(b[0]), "r"(b[1]));
}

__device__ __forceinline__ void sts8h(uint32_t addr, __half a, __half b,
                                      __half c, __half d) {
  __half2 p0(a, b), p1(c, d);
  asm volatile("st.shared.v2.b32 [%0], {%1, %2};" ::
               "r"(addr), "r"(*(uint32_t*)&p0), "r"(*(uint32_t*)&p1) : "memory");
}

// Window tile rows: 128B hold 64 k fp16 = two 32-k chunks; p = chunk parity
// selects the 64B half; ks = 16-k step within chunk. SW128 swizzled.
__device__ __forceinline__ uint32_t a_frag_addr(uint32_t tb, int mt, int ks, int p, int lid) {
  uint32_t off = (uint32_t)(mt + (lid & 15)) * 128 + p * 64 + ks * 32 + ((lid >> 4) * 16);
  return tb + SWZ(off);
}
__device__ __forceinline__ uint32_t b_frag_addr(uint32_t tb, int nt, int ks, int p, int lid) {
  uint32_t off = (uint32_t)(nt + ((lid >> 4) & 1) * 8 + (lid & 7)) * 128
               + p * 64 + ks * 32 + (((lid >> 3) & 1) * 16);
  return tb + SWZ(off);
}
// V subtile: rows = s (64 x 128B window), cols = 64 d fp16; trans-ldmatrix B frag.
__device__ __forceinline__ uint32_t v_frag_addr(uint32_t tvw, int half, int nt,
                                                int ks, int ckp, int lid) {
  uint32_t base = tvw + (uint32_t)half * 8192u;
  uint32_t row = (uint32_t)(ckp * 32 + ks * 16 + ((lid >> 3) & 1) * 8 + (lid & 7));
  uint32_t col = (uint32_t)(nt + ((lid >> 4) & 1) * 8) * 2;
  return base + SWZ(row * 128 + col);
}

// ---------------------------------------------------------------------------
// JAX threefry2x32 (20 rounds) — exact; partitionable counter layout.
// ---------------------------------------------------------------------------
__device__ __forceinline__ uint32_t rotl32(uint32_t x, int r) {
  return (x << r) | (x >> (32 - r));
}
__device__ __forceinline__ void threefry2x32(uint32_t k0, uint32_t k1,
                                             uint32_t& x0, uint32_t& x1) {
  const uint32_t ks0 = k0, ks1 = k1, ks2 = k0 ^ k1 ^ 0x1BD11BDAu;
  x0 += ks0; x1 += ks1;
#define TF_R(r) { x0 += x1; x1 = rotl32(x1, r); x1 ^= x0; }
  TF_R(13) TF_R(15) TF_R(26) TF_R(6)
  x0 += ks1; x1 += ks2 + 1u;
  TF_R(17) TF_R(29) TF_R(16) TF_R(24)
  x0 += ks2; x1 += ks0 + 2u;
  TF_R(13) TF_R(15) TF_R(26) TF_R(6)
  x0 += ks0; x1 += ks1 + 3u;
  TF_R(17) TF_R(29) TF_R(16) TF_R(24)
  x0 += ks1; x1 += ks2 + 4u;
  TF_R(13) TF_R(15) TF_R(26) TF_R(6)
  x0 += ks2; x1 += ks0 + 5u;
#undef TF_R
}
__device__ __forceinline__ bool keep_draw(uint32_t i) {
  uint32_t x0 = 0u, x1 = i;
  threefry2x32(0u, 42u, x0, x1);
  const uint32_t bits = x0 ^ x1;
  const float u = __uint_as_float((bits >> 9) | 0x3F800000u) - 1.0f;
  return u < 0.1f;
}

// ===========================================================================
// QKS kernel: QK^T + scale + mask + softmax + dropout -> P fp16 (1-term).
// Grid (2, HH), 512 threads, 1 CTA/SM (register-bound).
// SMEM: QF(0..2) 3x48KB @0 (3-deep fp32 staging) ; QA window 16KB @147456 ;
//       QB window 32KB @163840. Total 192KB.
// Single fp16 window pair: half (ck&1) is consumed this iteration while the
// other half (holding chunk ck-1, already consumed) is overwritten for ck+1.
// ===========================================================================
#define QF(s) (sbase + (uint32_t)(s) * 49152u)
#define QAW   (sbase + 147456u)
#define QBW   (sbase + 163840u)
#define QKS_SMEM 196608

__device__ __forceinline__ void qks_cp(
    uint32_t fbase, const float* __restrict__ Qf, const float* __restrict__ Kf,
    size_t qrow0, size_t krow0, int kb, int tid) {
#pragma unroll
  for (int i = 0; i < 6; i++) {
    int seg = tid + i * 512;            // 0..3071 : 1024 A + 2048 B
    int tile = (seg >= 1024);
    int w = tile ? seg - 1024 : seg;
    int r = w >> 3, c4 = w & 7;
    const float* g = tile ? (Kf + (krow0 + r) * DD) : (Qf + (qrow0 + r) * DD);
    cp_async16(fbase + (tile ? 16384u : 0u) + (uint32_t)w * 16u, g + kb + c4 * 4);
  }
  cp_commit();
}

__device__ __forceinline__ void qks_convert(uint32_t fbase, uint32_t sbase,
                                            int p, int tid) {
#pragma unroll
  for (int i = 0; i < 6; i++) {
    int seg = tid + i * 512;
    int tile = (seg >= 1024);
    int w = tile ? seg - 1024 : seg;
    uint32_t faddr = fbase + (tile ? 16384u : 0u) + (uint32_t)w * 16u;
    float4 v;
    asm volatile("ld.shared.v4.b32 {%0,%1,%2,%3}, [%4];"
                 : "=f"(v.x), "=f"(v.y), "=f"(v.z), "=f"(v.w) : "r"(faddr));
    __half h0 = __float2half(v.x), h1 = __float2half(v.y);
    __half h2 = __float2half(v.z), h3 = __float2half(v.w);
    int r = w >> 3, c4 = w & 7;
    uint32_t base = tile ? QBW : QAW;
    uint32_t o = (uint32_t)r * 128u + (uint32_t)p * 64u + (uint32_t)c4 * 8u;
    sts8h(base + SWZ(o), h0, h1, h2, h3);
  }
}

__global__ __launch_bounds__(512, 1) void qks_kernel(
    const float* __restrict__ Qf, const float* __restrict__ Kf,
    const float* __restrict__ mask, __half* __restrict__ phi) {
  extern __shared__ char smem[];
  const uint32_t sbase = smem_to_u32(smem);
  const int tid = threadIdx.x, wid = tid >> 5, lid = tid & 31;
  const int warp_m = wid >> 2, warp_n = wid & 3;
  const int m0 = warp_m * 32, n0 = warp_n * 64;
  const int q0 = blockIdx.x * 128;
  const int h = blockIdx.y;

  const size_t qrow0 = (size_t)h * SS + q0;
  const size_t krow0 = (size_t)h * SS;

  float acc[2][8][4];
#pragma unroll
  for (int mi = 0; mi < 2; mi++)
#pragma unroll
    for (int ni = 0; ni < 8; ni++)
#pragma unroll
      for (int j = 0; j < 4; j++) acc[mi][ni][j] = 0.0f;

  const int NC = DD / 32;  // 64
  qks_cp(QF(0), Qf, Kf, qrow0, krow0, 0, tid);
  qks_cp(QF(1), Qf, Kf, qrow0, krow0, 32, tid);
  qks_cp(QF(2), Qf, Kf, qrow0, krow0, 64, tid);
  cp_wait2();                       // stage 0 landed
  qks_convert(QF(0), sbase, 0, tid);
  __syncthreads();

  for (int ck = 0; ck < NC; ck++) {
    const bool have3 = (ck + 3 < NC);
    if (have3) qks_cp(QF((ck + 3) % 3), Qf, Kf, qrow0, krow0, (ck + 3) * 32, tid);
    // 1-term MMA on window half p = ck&1
    {
      const int p = ck & 1;
#pragma unroll
      for (int ks = 0; ks < 2; ks++) {
        uint32_t a[2][4], b[4][4];
#pragma unroll
        for (int mi = 0; mi < 2; mi++)
          ldsm_x4(a_frag_addr(QAW, m0 + mi * 16, ks, p, lid), a[mi]);
#pragma unroll
        for (int nj = 0; nj < 4; nj++)
          ldsm_x4(b_frag_addr(QBW, n0 + nj * 16, ks, p, lid), b[nj]);
#pragma unroll
        for (int mi = 0; mi < 2; mi++)
#pragma unroll
          for (int ni = 0; ni < 8; ni++) {
            uint32_t bb[2] = { b[ni >> 1][(ni & 1) * 2], b[ni >> 1][(ni & 1) * 2 + 1] };
            mma16816(acc[mi][ni], a[mi], bb);
          }
      }
    }
    if (ck + 1 < NC) {
      if (have3) cp_wait2();
      else if (ck + 2 < NC) cp_wait1();
      else cp_wait0();
      qks_convert(QF((ck + 1) % 3), sbase, (ck + 1) & 1, tid);
    }
    __syncthreads();
  }

  // ---- epilogue: scale + mask ----
  const float scale = 0.022097086912079608f;  // 1/sqrt(2048)
  const int rr = lid >> 2, cc = lid & 3;
#pragma unroll
  for (int mi = 0; mi < 2; mi++)
#pragma unroll
    for (int ni = 0; ni < 8; ni++)
#pragma unroll
      for (int j = 0; j < 4; j++) {
        const int r = q0 + m0 + mi * 16 + (j >> 1) * 8 + rr;
        const int c = n0 + ni * 8 + cc * 2 + (j & 1);
        acc[mi][ni][j] = acc[mi][ni][j] * scale + mask[(size_t)r * SS + c];
      }

  // ---- row softmax across 4 n-warps ----
  float* sred = (float*)smem;  // [128 rows][4]  (QF region is dead now)
  float rmax[2][2], rsum[2][2];
#pragma unroll
  for (int mi = 0; mi < 2; mi++)
#pragma unroll
    for (int hf = 0; hf < 2; hf++) {
      float m = -3.4e38f;
#pragma unroll
      for (int ni = 0; ni < 8; ni++) {
        m = fmaxf(m, acc[mi][ni][hf * 2 + 0]);
        m = fmaxf(m, acc[mi][ni][hf * 2 + 1]);
      }
      m = fmaxf(m, __shfl_xor_sync(0xffffffffu, m, 1));
      m = fmaxf(m, __shfl_xor_sync(0xffffffffu, m, 2));
      if (cc == 0) sred[(m0 + mi * 16 + hf * 8 + rr) * 4 + warp_n] = m;
    }
  __syncthreads();
#pragma unroll
  for (int mi = 0; mi < 2; mi++)
#pragma unroll
    for (int hf = 0; hf < 2; hf++) {
      const int row = m0 + mi * 16 + hf * 8 + rr;
      rmax[mi][hf] = fmaxf(fmaxf(sred[row * 4 + 0], sred[row * 4 + 1]),
                           fmaxf(sred[row * 4 + 2], sred[row * 4 + 3]));
    }
  __syncthreads();
#pragma unroll
  for (int mi = 0; mi < 2; mi++)
#pragma unroll
    for (int hf = 0; hf < 2; hf++) {
      float s = 0.0f;
#pragma unroll
      for (int ni = 0; ni < 8; ni++) {
        float e0 = expf(acc[mi][ni][hf * 2 + 0] - rmax[mi][hf]);
        float e1 = expf(acc[mi][ni][hf * 2 + 1] - rmax[mi][hf]);
        acc[mi][ni][hf * 2 + 0] = e0;
        acc[mi][ni][hf * 2 + 1] = e1;
        s += e0 + e1;
      }
      s += __shfl_xor_sync(0xffffffffu, s, 1);
      s += __shfl_xor_sync(0xffffffffu, s, 2);
      if (cc == 0) sred[(m0 + mi * 16 + hf * 8 + rr) * 4 + warp_n] = s;
    }
  __syncthreads();
#pragma unroll
  for (int mi = 0; mi < 2; mi++)
#pragma unroll
    for (int hf = 0; hf < 2; hf++) {
      const int row = m0 + mi * 16 + hf * 8 + rr;
      rsum[mi][hf] = sred[row * 4 + 0] + sred[row * 4 + 1] +
                     sred[row * 4 + 2] + sred[row * 4 + 3];
    }

  // ---- dropout + fp16 store ----
#pragma unroll
  for (int mi = 0; mi < 2; mi++)
#pragma unroll
    for (int hf = 0; hf < 2; hf++) {
      const int r = q0 + m0 + mi * 16 + hf * 8 + rr;
      const float inv = 1.0f / rsum[mi][hf];
      const uint32_t ibase = ((uint32_t)h * SS + (uint32_t)r) * SS;
#pragma unroll
      for (int ni = 0; ni < 8; ni++) {
        const int c = n0 + ni * 8 + cc * 2;
        float p0 = acc[mi][ni][hf * 2 + 0] * inv;
        float p1 = acc[mi][ni][hf * 2 + 1] * inv;
        p0 = keep_draw(ibase + c)     ? (p0 / 0.1f) : 0.0f;
        p1 = keep_draw(ibase + c + 1) ? (p1 / 0.1f) : 0.0f;
        const size_t o = ((size_t)h * SS + r) * SS + c;
        *(__half2*)(phi + o) = __half2(__float2half(p0), __float2half(p1));
      }
    }
}

// ===========================================================================
// PV kernel (r9, measured 151us): out[h, q0..+128, d0..+128] = P @ V.
// Grid (16, 2, HH), 256 threads, 2 CTAs/SM.
// SMEM: PA windows(0..1) 2x16KB @0 ; PFV(0..1) 2x16KB @32768 ;
//       PTV windows(0..1) 2x16KB @65536. Total 96KB.
// ===========================================================================
#define PA(w)  (sbase + (uint32_t)(w) * 16384u)
#define PFV(s) (sbase + 32768u + (uint32_t)(s) * 16384u)
#define PTV(w) (sbase + 65536u + (uint32_t)(w) * 16384u)
#define PV_SMEM 98304

__device__ __forceinline__ void pv_cp(
    uint32_t paw, int pb, uint32_t fv,
    const __half* __restrict__ Phi, size_t prow0,
    const float* __restrict__ Vf, size_t vrow0, int kb, int tid) {
  // P A hi tile: 512 x 16B into window half pb
#pragma unroll
  for (int i = 0; i < 2; i++) {
    int w = tid + i * 256;              // 0..511
    int r = w >> 2, c16 = w & 3;
    cp_async16(paw + SWZ((uint32_t)r * 128u + (uint32_t)pb * 64u + (uint32_t)c16 * 16u),
               Phi + (prow0 + r) * SS + kb + c16 * 8);
  }
  // V fp32: 1024 x 16B, 32 s-rows x 128 d
#pragma unroll
  for (int i = 0; i < 4; i++) {
    int w = tid + i * 256;
    int s = w >> 5, d4 = w & 31;
    cp_async16(fv + (uint32_t)w * 16u, Vf + (vrow0 + kb + s) * DD + d4 * 4);
  }
  cp_commit();
}

__device__ __forceinline__ void pv_vconvert(uint32_t fv, uint32_t tvw, int ckp, int tid) {
#pragma unroll
  for (int i = 0; i < 4; i++) {
    int w = tid + i * 256;
    int s = w >> 5, d4 = w & 31;
    float4 v;
    asm volatile("ld.shared.v4.b32 {%0,%1,%2,%3}, [%4];"
                 : "=f"(v.x), "=f"(v.y), "=f"(v.z), "=f"(v.w)
                 : "r"(fv + (uint32_t)w * 16u));
    __half h0 = __float2half(v.x), h1 = __float2half(v.y);
    __half h2 = __float2half(v.z), h3 = __float2half(v.w);
    int half = d4 >> 4, dl4 = d4 & 15;
    uint32_t off = SWZ(((uint32_t)(ckp * 32 + s)) * 128u + (uint32_t)dl4 * 8u);
    sts8h(tvw + (uint32_t)half * 8192u + off, h0, h1, h2, h3);
  }
}

__global__ __launch_bounds__(256, 2) void pv_kernel(
    const __half* __restrict__ Phi, const float* __restrict__ Vf,
    float* __restrict__ out) {
  extern __shared__ char smem[];
  const uint32_t sbase = smem_to_u32(smem);
  const int tid = threadIdx.x, wid = tid >> 5, lid = tid & 31;
  const int warp_m = wid >> 1, warp_n = wid & 1;
  const int d0 = blockIdx.x * 128;
  const int q0 = blockIdx.y * 128;
  const int h = blockIdx.z;

  const size_t prow0 = (size_t)h * SS + q0;
  const size_t vrow0 = (size_t)h * SS;

  float acc[2][8][4];
#pragma unroll
  for (int mi = 0; mi < 2; mi++)
#pragma unroll
    for (int ni = 0; ni < 8; ni++)
#pragma unroll
      for (int j = 0; j < 4; j++) acc[mi][ni][j] = 0.0f;

  const float* Vd = Vf + d0;
  const int NC = SS / 32;  // 8
  pv_cp(PA(0), 0, PFV(0), Phi, prow0, Vd, vrow0, 0, tid);
  pv_cp(PA(0), 1, PFV(1), Phi, prow0, Vd, vrow0, 32, tid);
  cp_wait1();
  pv_vconvert(PFV(0), PTV(0), 0, tid);
  __syncthreads();

  for (int ck = 0; ck < NC; ck++) {
    const bool have2 = (ck + 2 < NC);
    if (have2)
      pv_cp(PA(((ck + 2) >> 1) & 1), (ck + 2) & 1, PFV(ck & 1),
            Phi, prow0, Vd, vrow0, (ck + 2) * 32, tid);
    // 1-term MMA
    {
      const uint32_t taw = PA((ck >> 1) & 1);
      const uint32_t tvw = PTV((ck >> 1) & 1);
      const int pa = ck & 1, ckp = ck & 1;
      const int m0 = warp_m * 32;
#pragma unroll
      for (int ks = 0; ks < 2; ks++) {
        uint32_t a[2][4], b[4][4];
#pragma unroll
        for (int mi = 0; mi < 2; mi++)
          ldsm_x4(a_frag_addr(taw, m0 + mi * 16, ks, pa, lid), a[mi]);
#pragma unroll
        for (int nj = 0; nj < 4; nj++)
          ldsm_x4_t(v_frag_addr(tvw, warp_n, nj * 16, ks, ckp, lid), b[nj]);
#pragma unroll
        for (int mi = 0; mi < 2; mi++)
#pragma unroll
          for (int ni = 0; ni < 8; ni++) {
            uint32_t bb[2] = { b[ni >> 1][(ni & 1) * 2], b[ni >> 1][(ni & 1) * 2 + 1] };
            mma16816(acc[mi][ni], a[mi], bb);
          }
      }
    }
    if (ck + 1 < NC) {
      if (have2) cp_wait1(); else cp_wait0();
      pv_vconvert(PFV((ck + 1) & 1), PTV(((ck + 1) >> 1) & 1), (ck + 1) & 1, tid);
    }
    __syncthreads();
  }

#pragma unroll
  for (int mi = 0; mi < 2; mi++) {
    const int r0 = q0 + warp_m * 32 + mi * 16 + (lid >> 2);
#pragma unroll
    for (int ni = 0; ni < 8; ni++) {
      const int c = d0 + warp_n * 64 + ni * 8 + (lid & 3) * 2;
#pragma unroll
      for (int half = 0; half < 2; half++) {
        const int r = r0 + half * 8;
        *(float2*)(out + ((size_t)h * SS + r) * DD + c) =
            make_float2(acc[mi][ni][half * 2 + 0], acc[mi][ni][half * 2 + 1]);
      }
    }
  }
}

// ---------------------------------------------------------------------------
// Launch
// ---------------------------------------------------------------------------
extern "C" void kernel_launch(void* const* d_in, const int* in_sizes, int n_in,
                              void* d_out, int out_size) {
  const float* Q = (const float*)d_in[0];
  const float* K = (const float*)d_in[1];
  const float* V = (const float*)d_in[2];
  const float* mask = (const float*)d_in[3];
  float* out = (float*)d_out;

  __half* phi;
  cudaGetSymbolAddress((void**)&phi, g_phi);

  cudaFuncSetAttribute(qks_kernel, cudaFuncAttributeMaxDynamicSharedMemorySize, QKS_SMEM);
  cudaFuncSetAttribute(pv_kernel, cudaFuncAttributeMaxDynamicSharedMemorySize, PV_SMEM);

  // QK^T -> scale+mask -> softmax -> dropout -> P fp16 (1-term, 3-deep pipeline)
  qks_kernel<<<dim3(2, HH), 512, QKS_SMEM>>>(Q, K, mask, phi);
  // P @ V (1-term, r9 structure)
  pv_kernel<<<dim3(DD / 128, 2, HH), 256, PV_SMEM>>>(phi, V, out);
}